// round 17
// baseline (speedup 1.0000x reference)
#include <cuda_runtime.h>
#include <cstdint>

#define BATCH 4
#define NPTS  4096
#define FIN   64
#define FOUT  64
#define KNN   20
#define TOTAL (BATCH * NPTS)   // 16384 points

// ---------------- scratch (static device memory; no allocations) ----------------
__device__ unsigned short g_keyHi[(size_t)TOTAL * NPTS];  // 134 MB u16 ranking keys
__device__ float g_xT[BATCH * FIN * NPTS];      // x transposed: [b][f][n]
__device__ float g_u[TOTAL * FOUT];             // (W1-W2)x + b
__device__ float g_v[TOTAL * FOUT];             // W2 x
__device__ float g_xs[TOTAL];                   // squared norms
__device__ int   g_idx[TOTAL * KNN];            // knn indices (local to batch)

__device__ __forceinline__ unsigned short ord16(float v) {
    unsigned o = __float_as_uint(v);
    o = (o & 0x80000000u) ? ~o : (o | 0x80000000u);
    return (unsigned short)(o >> 16);
}
__device__ __forceinline__ unsigned ord32(float v) {
    unsigned o = __float_as_uint(v);
    return (o & 0x80000000u) ? ~o : (o | 0x80000000u);
}

// ---------------- kernel A: per-point transform (+ transposed x) ----------------
__global__ void transform_kernel(const float* __restrict__ x,
                                 const float* __restrict__ W,
                                 const float* __restrict__ bias) {
    __shared__ float Ws[FOUT * 2 * FIN];
    __shared__ float bs[FOUT];
    int t = threadIdx.x;
    for (int i = t; i < FOUT * 2 * FIN; i += blockDim.x) Ws[i] = W[i];
    if (t < FOUT) bs[t] = bias[t];
    __syncthreads();

    int p = blockIdx.x * blockDim.x + t;
    float xr[FIN];
    const float4* xp = (const float4*)(x + (size_t)p * FIN);
#pragma unroll
    for (int q = 0; q < FIN / 4; q++) {
        float4 v4 = xp[q];
        xr[4*q+0] = v4.x; xr[4*q+1] = v4.y; xr[4*q+2] = v4.z; xr[4*q+3] = v4.w;
    }
    float s = 0.f;
#pragma unroll
    for (int c = 0; c < FIN; c++) s += xr[c] * xr[c];
    g_xs[p] = s;

    float* xt = g_xT + (size_t)(p >> 12) * FIN * NPTS + (p & (NPTS - 1));
#pragma unroll
    for (int c = 0; c < FIN; c++) xt[(size_t)c * NPTS] = xr[c];

    for (int o = 0; o < FOUT; o++) {
        float a1 = 0.f, a2 = 0.f;
        const float* wrow = &Ws[o * 2 * FIN];
#pragma unroll
        for (int c = 0; c < FIN; c++) {
            a1 += xr[c] * wrow[c];
            a2 += xr[c] * wrow[FIN + c];
        }
        g_u[p * FOUT + o] = a1 - a2 + bs[o];
        g_v[p * FOUT + o] = a2;
    }
}

// ---------------- kernel B: symmetric Gram -> u16 keys (R10 core, u16 epilogue) ----------------
#define TILE 128
#define SSTR 132
#define DIST_SMEM (2 * FIN * SSTR * 4)   // 67584 bytes

__global__ __launch_bounds__(256) void dist_kernel() {
    extern __shared__ float sm[];
    float* At = sm;
    float* Bt = sm + FIN * SSTR;

    int b = blockIdx.z;
    int id = blockIdx.x;            // upper-tri (by,bx), bx >= by
    int by = 0, rem = id;
    while (rem >= 32 - by) { rem -= 32 - by; by++; }
    int bx = by + rem;

    const float* XT = g_xT + (size_t)b * FIN * NPTS;
    int row0 = by * TILE, col0 = bx * TILE;
    int t  = threadIdx.x;
    int tr = t >> 4, tc = t & 15;

    for (int q = t; q < FIN * 32; q += 256) {
        int f  = q >> 5;
        int rc = (q & 31) * 4;
        *(float4*)&At[f * SSTR + rc] = *(const float4*)(XT + (size_t)f * NPTS + row0 + rc);
        *(float4*)&Bt[f * SSTR + rc] = *(const float4*)(XT + (size_t)f * NPTS + col0 + rc);
    }
    __syncthreads();

    float acc[8][8];
#pragma unroll
    for (int i = 0; i < 8; i++)
#pragma unroll
        for (int j = 0; j < 8; j++) acc[i][j] = 0.f;

    const float* Ar = At + tr * 8;
    const float* Br = Bt + tc * 4;
#pragma unroll 4
    for (int f = 0; f < FIN; f++) {
        float4 a0 = *(const float4*)(Ar + f * SSTR);
        float4 a1 = *(const float4*)(Ar + f * SSTR + 4);
        float4 b0 = *(const float4*)(Br + f * SSTR);
        float4 b1 = *(const float4*)(Br + f * SSTR + 64);
        float av[8] = {a0.x,a0.y,a0.z,a0.w,a1.x,a1.y,a1.z,a1.w};
        float bv[8] = {b0.x,b0.y,b0.z,b0.w,b1.x,b1.y,b1.z,b1.w};
#pragma unroll
        for (int i = 0; i < 8; i++)
#pragma unroll
            for (int j = 0; j < 8; j++)
                acc[i][j] = fmaf(av[i], bv[j], acc[i][j]);
    }

    int colG[8];
#pragma unroll
    for (int j = 0; j < 4; j++) { colG[j] = col0 + tc * 4 + j; colG[j+4] = col0 + 64 + tc * 4 + j; }

    float xsr[8], xsc[8];
#pragma unroll
    for (int i = 0; i < 8; i++) xsr[i] = g_xs[b * NPTS + row0 + tr * 8 + i];
#pragma unroll
    for (int j = 0; j < 8; j++) xsc[j] = g_xs[b * NPTS + colG[j]];

    // direct block: keyHi[row][col] = ord16(xs[col] - 2*acc)
#pragma unroll
    for (int i = 0; i < 8; i++) {
        size_t base = (size_t)(b * NPTS + row0 + tr * 8 + i) * NPTS;
        unsigned short h[8];
#pragma unroll
        for (int j = 0; j < 8; j++) h[j] = ord16(xsc[j] - 2.f * acc[i][j]);
        unsigned w0 = (unsigned)h[0] | ((unsigned)h[1] << 16);
        unsigned w1 = (unsigned)h[2] | ((unsigned)h[3] << 16);
        unsigned w2 = (unsigned)h[4] | ((unsigned)h[5] << 16);
        unsigned w3 = (unsigned)h[6] | ((unsigned)h[7] << 16);
        __stcs((uint2*)&g_keyHi[base + col0 + tc * 4],      make_uint2(w0, w1));
        __stcs((uint2*)&g_keyHi[base + col0 + 64 + tc * 4], make_uint2(w2, w3));
    }
    // mirrored block: keyHi[col][row] = ord16(xs[row] - 2*acc)
    if (bx != by) {
#pragma unroll
        for (int j = 0; j < 8; j++) {
            size_t base = (size_t)(b * NPTS + colG[j]) * NPTS + row0 + tr * 8;
            unsigned short h[8];
#pragma unroll
            for (int i = 0; i < 8; i++) h[i] = ord16(xsr[i] - 2.f * acc[i][j]);
            unsigned w0 = (unsigned)h[0] | ((unsigned)h[1] << 16);
            unsigned w1 = (unsigned)h[2] | ((unsigned)h[3] << 16);
            unsigned w2 = (unsigned)h[4] | ((unsigned)h[5] << 16);
            unsigned w3 = (unsigned)h[6] | ((unsigned)h[7] << 16);
            __stcs((uint4*)&g_keyHi[base], make_uint4(w0, w1, w2, w3));
        }
    }
}

// ---------------- kernel C: u16 radix filter + exact recompute ----------------
// 2x8-bit radix over u16 keys -> theta16 (bin of 20th smallest). Candidates =
// {key <= theta16, j != i} (superset of top-20). Exact distance recomputed for
// candidates; final rank by (ord32(dist), idx) u64 = stable-argsort semantics.
#define CAND_CAP 1024

__global__ __launch_bounds__(256) void select_kernel(const float* __restrict__ x) {
    int row = blockIdx.x;
    int b = row >> 12;
    int iLocal = row & (NPTS - 1);
    const uint4* keys = (const uint4*)(g_keyHi + (size_t)row * NPTS);
    int t = threadIdx.x;

    // 16 u16 keys per thread from two uint4 loads
    unsigned short k[16];
#pragma unroll
    for (int q = 0; q < 2; q++) {
        uint4 kv = __ldcs(&keys[t + q * 256]);
        unsigned wv[4] = {kv.x, kv.y, kv.z, kv.w};
        int j0 = (t + q * 256) * 8;
#pragma unroll
        for (int e = 0; e < 4; e++) {
            int ja = j0 + 2 * e, jb = ja + 1;
            k[q * 8 + 2*e]     = (ja == iLocal) ? (unsigned short)0xFFFF : (unsigned short)(wv[e] & 0xFFFFu);
            k[q * 8 + 2*e + 1] = (jb == iLocal) ? (unsigned short)0xFFFF : (unsigned short)(wv[e] >> 16);
        }
    }

    __shared__ int hist[256];
    __shared__ int sD, sCb, sNeed;
    __shared__ int cntC;
    __shared__ unsigned short cand[CAND_CAP];
    __shared__ unsigned long long cand64[CAND_CAP];
    __shared__ float xiS[FIN];

    unsigned prefix = 0, pmask = 0;
    if (t == 0) sNeed = KNN;

    // pass 0: bits [15:8]; pass 1: bits [7:0]
    for (int pass = 0; pass < 2; pass++) {
        int shift = 8 - 8 * pass;
        hist[t] = 0;
        __syncthreads();
#pragma unroll
        for (int q = 0; q < 16; q++) {
            bool ok = ((unsigned)k[q] & pmask) == prefix;
            unsigned act = __ballot_sync(0xffffffffu, ok);
            if (ok) {
                unsigned d = ((unsigned)k[q] >> shift) & 255u;
                unsigned m = __match_any_sync(act, d);
                if ((t & 31) == (__ffs(m) - 1))
                    atomicAdd(&hist[d], __popc(m));
            }
        }
        __syncthreads();
        if (t < 32) {
            int s[8], tot = 0, base = t * 8;
#pragma unroll
            for (int q2 = 0; q2 < 8; q2++) { s[q2] = hist[base + q2]; tot += s[q2]; }
            int inc = tot;
#pragma unroll
            for (int off = 1; off < 32; off <<= 1) {
                int o = __shfl_up_sync(0xffffffffu, inc, off);
                if (t >= off) inc += o;
            }
            int ex = inc - tot;
            int nd = sNeed;
            if (ex < nd && nd <= inc) {
                int run = ex;
#pragma unroll
                for (int q2 = 0; q2 < 8; q2++) {
                    if (nd <= run + s[q2]) { sD = base + q2; sCb = run; break; }
                    run += s[q2];
                }
            }
        }
        __syncthreads();
        prefix |= ((unsigned)sD) << shift;
        pmask  |= 0xFFu << shift;
        if (t == 0) { sNeed -= sCb; cntC = 0; }
    }
    __syncthreads();

    unsigned theta = prefix;   // u16 value of the 20th-smallest's bin

    // collect candidate indices (key <= theta)
#pragma unroll
    for (int q = 0; q < 16; q++) {
        if ((unsigned)k[q] <= theta) {
            int j = ((t + (q >> 3) * 256) * 8) + (q & 7);
            if (j != iLocal) {
                int s2 = atomicAdd(&cntC, 1);
                if (s2 < CAND_CAP) cand[s2] = (unsigned short)j;
            }
        }
    }
    // load x_i row
    if (t < FIN / 4) {
        float4 vv = ((const float4*)(x + (size_t)(b * NPTS + iLocal) * FIN))[t];
        xiS[4*t+0] = vv.x; xiS[4*t+1] = vv.y; xiS[4*t+2] = vv.z; xiS[4*t+3] = vv.w;
    }
    __syncthreads();

    int nC = cntC < CAND_CAP ? cntC : CAND_CAP;

    // exact recompute for each candidate
    for (int c = t; c < nC; c += 256) {
        int j = cand[c];
        const float4* xj = (const float4*)(x + (size_t)(b * NPTS + j) * FIN);
        float d0 = 0.f, d1 = 0.f, d2 = 0.f, d3 = 0.f;
#pragma unroll
        for (int q = 0; q < FIN / 4; q++) {
            float4 vv = xj[q];
            d0 = fmaf(xiS[4*q+0], vv.x, d0);
            d1 = fmaf(xiS[4*q+1], vv.y, d1);
            d2 = fmaf(xiS[4*q+2], vv.z, d2);
            d3 = fmaf(xiS[4*q+3], vv.w, d3);
        }
        float dot = (d0 + d1) + (d2 + d3);
        float key = g_xs[b * NPTS + j] - 2.f * dot;
        cand64[c] = ((unsigned long long)ord32(key) << 32) | (unsigned)j;
    }
    __syncthreads();

    // warp 0: iterative top-KNN by (value, idx)
    if (t < 32) {
        int* outp = g_idx + row * KNN;
        for (int sel = 0; sel < KNN; sel++) {
            unsigned long long m = ~0ULL;
            int ms = -1;
            for (int s2 = t; s2 < nC; s2 += 32) {
                unsigned long long vv = cand64[s2];
                if (vv < m) { m = vv; ms = s2; }
            }
            unsigned long long r = m;
#pragma unroll
            for (int off = 16; off; off >>= 1) {
                unsigned long long o = __shfl_xor_sync(0xffffffffu, r, off);
                r = (o < r) ? o : r;
            }
            unsigned win = __ballot_sync(0xffffffffu, m == r);
            int wl = __ffs(win) - 1;
            if (t == wl) {
                cand64[ms] = ~0ULL;
                outp[sel] = (int)(r & 0xFFFFFFFFu);
            }
            __syncwarp();
        }
    }
}

// ---------------- kernel D: gather-max epilogue ----------------
__global__ void gather_kernel(float* __restrict__ out) {
    int gid = blockIdx.x * blockDim.x + threadIdx.x;
    int p = gid >> 6;
    int o = gid & 63;
    int bbase = p & ~(NPTS - 1);
    const int* ip = g_idx + p * KNN;
    float m = -3.402823466e38f;
#pragma unroll
    for (int q = 0; q < KNN; q++) {
        int j = ip[q];
        m = fmaxf(m, g_v[(size_t)(bbase + j) * FOUT + o]);
    }
    out[gid] = g_u[gid] + m;
}

// ---------------- launch ----------------
extern "C" void kernel_launch(void* const* d_in, const int* in_sizes, int n_in,
                              void* d_out, int out_size) {
    const float* x    = (const float*)d_in[0];
    const float* W    = (const float*)d_in[1];
    const float* bias = (const float*)d_in[2];
    float* out = (float*)d_out;

    static bool s_init = false;
    if (!s_init) {
        s_init = true;
        cudaFuncSetAttribute(dist_kernel,
                             cudaFuncAttributeMaxDynamicSharedMemorySize, DIST_SMEM);
    }

    transform_kernel<<<TOTAL / 128, 128>>>(x, W, bias);
    dist_kernel<<<dim3(528, 1, BATCH), 256, DIST_SMEM>>>();
    select_kernel<<<TOTAL, 256>>>(x);
    gather_kernel<<<(TOTAL * FOUT) / 256, 256>>>(out);
}